// round 16
// baseline (speedup 1.0000x reference)
#include <cuda_runtime.h>
#include <cuda_fp16.h>
#include <cstdint>

// ---------------------------------------------------------------------------
// Problem constants
// ---------------------------------------------------------------------------
#define NMODES   128
#define TWO_N    256
#define NLAYERS  8
#define BATCH    131072
#define M_TILE   64
#define NTILES_M (BATCH / M_TILE)      // 2048
#define GRID_P   296                   // 2 CTAs per SM, split-N; one wave
#define STRIDE_T 148
#define NTHREADS 256

#define S_C  0.70710678118654752440f
#define WSCALE 0.0625f                 // W stored * 1/16 (fp16 range safety)
#define WSCALE_INV 16.0f

// ---------------------------------------------------------------------------
// Shared memory per CTA: Wh 32K | Wl 32K | A[2] 32K = 96K
// ---------------------------------------------------------------------------
#define OFF_WH   0
#define OFF_WL   32768
#define OFF_A    65536
#define SMEM_BYTES (OFF_A + 2 * 16384)   // 98304

// ---------------------------------------------------------------------------
// Global scratch
// ---------------------------------------------------------------------------
__device__ __half    g_Wh[TWO_N * NMODES];
__device__ __half    g_Wl[TWO_N * NMODES];
__device__ float     g_part[32 * NMODES];
__device__ unsigned  g_bar;

// ---------------------------------------------------------------------------
// Beamsplitter chain: branchless masked-coefficient warp scan
// ---------------------------------------------------------------------------
__device__ __forceinline__ void bs_chain2(float x[4], float p[4],
                                          float a0, float c1m, float c2m,
                                          float c4m, float c8m, float c16m,
                                          float e0, float s31, float m31)
{
    const unsigned FULL = 0xffffffffu;
    float xl0 = a0 * x[0];
    float pl0 = a0 * p[0];
    float xl1 = S_C * (xl0 + x[1]);
    float pl1 = S_C * (pl0 + p[1]);
    float xl2 = S_C * (xl1 + x[2]);
    float pl2 = S_C * (pl1 + p[2]);
    float xl3 = S_C * (xl2 + x[3]);
    float pl3 = S_C * (pl2 + p[3]);
    float xc = xl3, pc = pl3;
    xc = fmaf(c1m,  __shfl_up_sync(FULL, xc, 1),  xc);
    pc = fmaf(c1m,  __shfl_up_sync(FULL, pc, 1),  pc);
    xc = fmaf(c2m,  __shfl_up_sync(FULL, xc, 2),  xc);
    pc = fmaf(c2m,  __shfl_up_sync(FULL, pc, 2),  pc);
    xc = fmaf(c4m,  __shfl_up_sync(FULL, xc, 4),  xc);
    pc = fmaf(c4m,  __shfl_up_sync(FULL, pc, 4),  pc);
    xc = fmaf(c8m,  __shfl_up_sync(FULL, xc, 8),  xc);
    pc = fmaf(c8m,  __shfl_up_sync(FULL, pc, 8),  pc);
    xc = fmaf(c16m, __shfl_up_sync(FULL, xc, 16), xc);
    pc = fmaf(c16m, __shfl_up_sync(FULL, pc, 16), pc);
    float xe = e0 * __shfl_up_sync(FULL, xc, 1);
    float pe = e0 * __shfl_up_sync(FULL, pc, 1);
    float xu0 = fmaf(S_C, xe, xl0),                  pu0 = fmaf(S_C, pe, pl0);
    float xu1 = fmaf(0.5f, xe, xl1),                 pu1 = fmaf(0.5f, pe, pl1);
    float xu2 = fmaf(0.35355339059327373f, xe, xl2), pu2 = fmaf(0.35355339059327373f, pe, pl2);
    float xu3 = fmaf(0.25f, xe, xl3),                pu3 = fmaf(0.25f, pe, pl3);
    float xtn = __shfl_down_sync(FULL, x[0], 1);
    float ptn = __shfl_down_sync(FULL, p[0], 1);
    x[0] = S_C * (xu0 - x[1]);   p[0] = S_C * (pu0 - p[1]);
    x[1] = S_C * (xu1 - x[2]);   p[1] = S_C * (pu1 - p[2]);
    x[2] = S_C * (xu2 - x[3]);   p[2] = S_C * (pu2 - p[3]);
    x[3] = s31 * (xu3 - m31 * xtn);
    p[3] = s31 * (pu3 - m31 * ptn);
}

// ---------------------------------------------------------------------------
// GEMM helpers
// ---------------------------------------------------------------------------
__device__ __forceinline__ void ldsm_x4(unsigned addr, unsigned& r0, unsigned& r1,
                                        unsigned& r2, unsigned& r3)
{
    asm volatile("ldmatrix.sync.aligned.m8n8.x4.shared.b16 {%0,%1,%2,%3}, [%4];"
                 : "=r"(r0), "=r"(r1), "=r"(r2), "=r"(r3) : "r"(addr));
}
__device__ __forceinline__ void mma_f16(float* d, const unsigned* a,
                                        unsigned b0, unsigned b1)
{
    asm volatile("mma.sync.aligned.m16n8k16.row.col.f32.f16.f16.f32 "
                 "{%0,%1,%2,%3}, {%4,%5,%6,%7}, {%8,%9}, {%0,%1,%2,%3};"
                 : "+f"(d[0]), "+f"(d[1]), "+f"(d[2]), "+f"(d[3])
                 : "r"(a[0]), "r"(a[1]), "r"(a[2]), "r"(a[3]), "r"(b0), "r"(b1));
}

__device__ __forceinline__ void load_A(float4 pf[8], const float* __restrict__ x,
                                       int tile, int tid)
{
    size_t m0 = (size_t)tile * M_TILE;
#pragma unroll
    for (int it = 0; it < 4; ++it) {
        int idx = tid + it * NTHREADS;
        int rr = idx >> 4, cc = idx & 15;
        const float4* g = (const float4*)(x + (m0 + rr) * NMODES + cc * 8);
        pf[2 * it]     = __ldg(g);
        pf[2 * it + 1] = __ldg(g + 1);
    }
}

__device__ __forceinline__ void convert_A(char* smem, unsigned offA,
                                          const float4 pf[8], int tid)
{
#pragma unroll
    for (int it = 0; it < 4; ++it) {
        int idx = tid + it * NTHREADS;
        int rr = idx >> 4, cc = idx & 15;
        float vs[8] = {pf[2*it].x, pf[2*it].y, pf[2*it].z, pf[2*it].w,
                       pf[2*it+1].x, pf[2*it+1].y, pf[2*it+1].z, pf[2*it+1].w};
        unsigned h[4];
#pragma unroll
        for (int k = 0; k < 4; ++k)
            asm("cvt.rn.f16x2.f32 %0, %1, %2;"
                : "=r"(h[k]) : "f"(vs[2 * k + 1]), "f"(vs[2 * k]));
        unsigned off = rr * 256 + ((cc ^ (rr & 7)) << 4);
        *(uint4*)(smem + offA + off) = make_uint4(h[0], h[1], h[2], h[3]);
    }
}

// ---------------------------------------------------------------------------
// Fused kernel: phase A (CTAs 0..31 build W) | grid barrier | phase B (GEMM)
// Phase B: warp tile m64 x n16; W fragments live in 64 REGISTERS per warp
// (loaded once) -> main-loop LDSM traffic is A-only (-33% LDS bytes).
// ---------------------------------------------------------------------------
__global__ __launch_bounds__(NTHREADS, 2) void fused_kernel(
    const float* __restrict__ x,
    const float* __restrict__ params,
    float* __restrict__ out)
{
    extern __shared__ char smem[];
    const unsigned sbase = (unsigned)__cvta_generic_to_shared(smem);
    __shared__ float c_s[64];
    int tid = threadIdx.x, lane = tid & 31, wid = tid >> 5;
    int cta = blockIdx.x;
    const int q = cta & 1;

    // ---- everyone: issue first A-tile loads (overlaps phase A) ----
    int t = cta >> 1;
    float4 pf[8];
    load_A(pf, x, t, tid);

    // ================= phase A: build W (CTAs 0..31) =================
    if (cta < 32) {
        float4* sblk  = (float4*)(smem + OFF_A);
        float*  wpart = (float*)(smem + OFF_A + 16384);
#pragma unroll
        for (int q4 = 0; q4 < 4; ++q4) {
            int idx = tid + q4 * 256;
            int l = idx >> 7, b = idx & 127;
            float th1 = params[l * (3 * NMODES) + 3 * b + 0];
            float r   = params[l * (3 * NMODES) + 3 * b + 1];
            float th2 = params[l * (3 * NMODES) + 3 * b + 2];
            float s1, c1, s2, c2;
            __sincosf(th1, &s1, &c1);
            __sincosf(th2, &s2, &c2);
            float em = __expf(-r), ep = __expf(r);
            float A00 =  em * c1, A01 = -em * s1;
            float A10 =  ep * s1, A11 =  ep * c1;
            sblk[idx] = make_float4(c2 * A00 - s2 * A10,
                                    c2 * A01 - s2 * A11,
                                    s2 * A00 + c2 * A10,
                                    s2 * A01 + c2 * A11);
        }
        __syncthreads();

        int c = cta * 8 + wid;
        float a0   = (lane == 0)  ? 1.f : S_C;
        float c1m  = (lane >= 1)  ? 0.25f : 0.f;
        float c2m  = (lane >= 2)  ? 0.0625f : 0.f;
        float c4m  = (lane >= 4)  ? 0.00390625f : 0.f;
        float c8m  = (lane >= 8)  ? 1.52587890625e-05f : 0.f;
        float c16m = (lane >= 16) ? 2.3283064365386963e-10f : 0.f;
        float e0   = (lane == 0)  ? 0.f : 1.f;
        float s31  = (lane == 31) ? 1.f : S_C;
        float m31  = (lane == 31) ? 0.f : 1.f;

        float xx[4], pp[4];
#pragma unroll
        for (int j = 0; j < 4; ++j) {
            int b = 4 * lane + j;
            xx[j] = (c == 2 * b)     ? 1.f : 0.f;
            pp[j] = (c == 2 * b + 1) ? 1.f : 0.f;
        }
        for (int l = 0; l < NLAYERS; ++l) {
#pragma unroll
            for (int j = 0; j < 4; ++j) {
                float4 Bv = sblk[l * NMODES + 4 * lane + j];
                float nx = Bv.x * xx[j] + Bv.y * pp[j];
                float np = Bv.z * xx[j] + Bv.w * pp[j];
                xx[j] = nx; pp[j] = np;
            }
            bs_chain2(xx, pp, a0, c1m, c2m, c4m, c8m, c16m, e0, s31, m31);
        }

        if ((wid & 1) == 0) {
            int k = c >> 1;
#pragma unroll
            for (int j = 0; j < 4; ++j) {
                int b = 4 * lane + j;
                float wx = xx[j] * WSCALE;
                float wp = pp[j] * WSCALE;
                __half hx = __float2half_rn(wx);
                __half hp = __float2half_rn(wp);
                g_Wh[(2 * b)     * NMODES + k] = hx;
                g_Wh[(2 * b + 1) * NMODES + k] = hp;
                g_Wl[(2 * b)     * NMODES + k] = __float2half_rn(wx - __half2float(hx));
                g_Wl[(2 * b + 1) * NMODES + k] = __float2half_rn(wp - __half2float(hp));
            }
        }
#pragma unroll
        for (int j = 0; j < 4; ++j)
            wpart[wid * NMODES + 4 * lane + j] = xx[j] * xx[j] + pp[j] * pp[j];
        __syncthreads();
        if (tid < NMODES) {
            float s = 0.f;
#pragma unroll
            for (int w = 0; w < 8; ++w) s += wpart[w * NMODES + tid];
            g_part[cta * NMODES + tid] = s;
        }
    }

    // ================= grid barrier (epoch-based, replay-safe) =============
    __threadfence();
    __syncthreads();
    if (tid == 0) {
        unsigned v = atomicAdd(&g_bar, 1u);
        unsigned target = v - (v % (unsigned)GRID_P) + (unsigned)GRID_P;
        for (;;) {
            unsigned cur;
            asm volatile("ld.global.acquire.gpu.u32 %0, [%1];"
                         : "=r"(cur) : "l"(&g_bar));
            if (cur >= target) break;
            __nanosleep(128);
        }
    }
    __syncthreads();
    __threadfence();

    // ================= phase B: persistent GEMM =================
    // warp wid owns n16 (8 modes); all warps cover full m64.
    const int wn = wid;

    // stage this half's W (hi+lo), permuted so thread D-col pairs hit
    // ADJACENT modes: smem row p (0..15 in group): nt=p>>3, c=(p&7)>>1,
    // par=p&1 -> mode_local = c*2 + nt, W row j = q*128+wg*16+2*ml+par
#pragma unroll
    for (int it = 0; it < 16; ++it) {
        int idx = tid + it * NTHREADS;
        int arr = idx >> 11;
        int rem = idx & 2047;
        int rr  = rem >> 4;
        int cc  = idx & 15;
        int wg  = rr >> 4, p = rr & 15;
        int nt  = p >> 3, cx = (p & 7) >> 1, par = p & 1;
        int ml  = cx * 2 + nt;
        int j   = q * 128 + wg * 16 + 2 * ml + par;
        uint4 v = *(const uint4*)((arr ? g_Wl : g_Wh) + j * NMODES + cc * 8);
        *(uint4*)(smem + (arr ? OFF_WL : OFF_WH) + rr * 256 + ((cc ^ (rr & 7)) << 4)) = v;
    }
    if (tid < 64) {
        float s = 0.f;
#pragma unroll
        for (int cb = 0; cb < 32; ++cb)
            s += g_part[cb * NMODES + q * 64 + tid];
        c_s[tid] = 0.25f * s - 0.5f;
    }

    // ldsm lane mappings
    int a_row = (lane & 15);
    int a_cc  = (lane >> 4);
    int b_row = ((lane >> 4) << 3) + (lane & 7);
    int b_cc  = ((lane >> 3) & 1);

    __syncthreads();            // W smem visible

    // ---- load W fragments into persistent registers (once) ----
    unsigned WH[8][4], WL[8][4];
#pragma unroll
    for (int ks = 0; ks < 8; ++ks) {
        int br = wn * 16 + b_row;
        int cc = 2 * ks + b_cc;
        unsigned soff = br * 256 + ((cc ^ (br & 7)) << 4);
        ldsm_x4(sbase + OFF_WH + soff, WH[ks][0], WH[ks][1], WH[ks][2], WH[ks][3]);
        ldsm_x4(sbase + OFF_WL + soff, WL[ks][0], WL[ks][1], WL[ks][2], WL[ks][3]);
    }

    float cvals[2];
    cvals[0] = c_s[wn * 8 + (lane & 3) * 2];
    cvals[1] = c_s[wn * 8 + (lane & 3) * 2 + 1];

    // prologue: convert first tile into A[0], prefetch second
    convert_A(smem, OFF_A, pf, tid);
    if (t + STRIDE_T < NTILES_M) load_A(pf, x, t + STRIDE_T, tid);
    __syncthreads();

    int buf = 0;
    while (t < NTILES_M) {
        // convert tile t+1 into the other buffer (pf dies; dead in MMA loop)
        if (t + STRIDE_T < NTILES_M)
            convert_A(smem, OFF_A + (buf ^ 1) * 16384, pf, tid);

        float acc[4][2][4];
#pragma unroll
        for (int mf = 0; mf < 4; ++mf)
#pragma unroll
            for (int nt = 0; nt < 2; ++nt)
#pragma unroll
                for (int v = 0; v < 4; ++v) acc[mf][nt][v] = 0.f;

        const unsigned AB = sbase + OFF_A + buf * 16384;
#pragma unroll
        for (int ks = 0; ks < 8; ++ks) {
            unsigned af[4][4];
#pragma unroll
            for (int mf = 0; mf < 4; ++mf) {
                int ar = mf * 16 + a_row;
                int cc = 2 * ks + a_cc;
                ldsm_x4(AB + ar * 256 + ((cc ^ (ar & 7)) << 4),
                        af[mf][0], af[mf][1], af[mf][2], af[mf][3]);
            }
#pragma unroll
            for (int mf = 0; mf < 4; ++mf) {
                mma_f16(acc[mf][0], af[mf], WH[ks][0], WH[ks][1]);
                mma_f16(acc[mf][1], af[mf], WH[ks][2], WH[ks][3]);
            }
#pragma unroll
            for (int mf = 0; mf < 4; ++mf) {
                mma_f16(acc[mf][0], af[mf], WL[ks][0], WL[ks][1]);
                mma_f16(acc[mf][1], af[mf], WL[ks][2], WL[ks][3]);
            }
        }

        // prefetch tile t+2*stride (pf reborn; covered by epilogue+sync+conv)
        if (t + 2 * STRIDE_T < NTILES_M) load_A(pf, x, t + 2 * STRIDE_T, tid);

        // epilogue: adjacent-mode float2 stores
        {
            size_t m0 = (size_t)t * M_TILE;
            int mode0 = q * 64 + wn * 8 + (lane & 3) * 2;
#pragma unroll
            for (int mf = 0; mf < 4; ++mf) {
#pragma unroll
                for (int h = 0; h < 2; ++h) {
                    int row = mf * 16 + (lane >> 2) + h * 8;
                    float f0 = acc[mf][0][2 * h]     * WSCALE_INV;
                    float f1 = acc[mf][0][2 * h + 1] * WSCALE_INV;
                    float g0 = acc[mf][1][2 * h]     * WSCALE_INV;
                    float g1 = acc[mf][1][2 * h + 1] * WSCALE_INV;
                    float2 v;
                    v.x = fmaf(f0, f0, fmaf(f1, f1, cvals[0]));
                    v.y = fmaf(g0, g0, fmaf(g1, g1, cvals[1]));
                    *(float2*)(out + (m0 + row) * NMODES + mode0) = v;
                }
            }
        }

        __syncthreads();           // converts visible before next MMA loop
        t += STRIDE_T;
        buf ^= 1;
    }
}

// ---------------------------------------------------------------------------
// Launch
// ---------------------------------------------------------------------------
extern "C" void kernel_launch(void* const* d_in, const int* in_sizes, int n_in,
                              void* d_out, int out_size)
{
    const float* inputs = (const float*)d_in[0];
    const float* params = (const float*)d_in[1];
    float* out = (float*)d_out;

    cudaFuncSetAttribute(fused_kernel, cudaFuncAttributeMaxDynamicSharedMemorySize,
                         SMEM_BYTES);

    fused_kernel<<<GRID_P, NTHREADS, SMEM_BYTES>>>(inputs, params, out);
}

// round 17
// speedup vs baseline: 1.7696x; 1.7696x over previous
#include <cuda_runtime.h>
#include <cuda_fp16.h>
#include <cstdint>

// ---------------------------------------------------------------------------
// Problem constants
// ---------------------------------------------------------------------------
#define NMODES   128
#define TWO_N    256
#define NLAYERS  8
#define BATCH    131072
#define M_TILE   64
#define NTILES_M (BATCH / M_TILE)      // 2048
#define GRID_P   296                   // 2 CTAs per SM, split-N; one wave
#define STRIDE_T 148
#define NTHREADS 256

#define S_C  0.70710678118654752440f
#define WSCALE 0.0625f                 // W stored * 1/16 (fp16 range safety)
#define WSCALE_INV 16.0f

// ---------------------------------------------------------------------------
// Shared memory per CTA: Wh 32K | A[2] 32K = 64K
// (build phase reuses the A region for sblk/wpart scratch)
// ---------------------------------------------------------------------------
#define OFF_WH   0
#define OFF_A    32768
#define SMEM_BYTES (OFF_A + 2 * 16384)   // 65536

// ---------------------------------------------------------------------------
// Global scratch
// ---------------------------------------------------------------------------
__device__ __half    g_Wh[TWO_N * NMODES];
__device__ float     g_part[32 * NMODES];
__device__ unsigned  g_bar;

// ---------------------------------------------------------------------------
// Beamsplitter chain: branchless masked-coefficient warp scan
// ---------------------------------------------------------------------------
__device__ __forceinline__ void bs_chain2(float x[4], float p[4],
                                          float a0, float c1m, float c2m,
                                          float c4m, float c8m, float c16m,
                                          float e0, float s31, float m31)
{
    const unsigned FULL = 0xffffffffu;
    float xl0 = a0 * x[0];
    float pl0 = a0 * p[0];
    float xl1 = S_C * (xl0 + x[1]);
    float pl1 = S_C * (pl0 + p[1]);
    float xl2 = S_C * (xl1 + x[2]);
    float pl2 = S_C * (pl1 + p[2]);
    float xl3 = S_C * (xl2 + x[3]);
    float pl3 = S_C * (pl2 + p[3]);
    float xc = xl3, pc = pl3;
    xc = fmaf(c1m,  __shfl_up_sync(FULL, xc, 1),  xc);
    pc = fmaf(c1m,  __shfl_up_sync(FULL, pc, 1),  pc);
    xc = fmaf(c2m,  __shfl_up_sync(FULL, xc, 2),  xc);
    pc = fmaf(c2m,  __shfl_up_sync(FULL, pc, 2),  pc);
    xc = fmaf(c4m,  __shfl_up_sync(FULL, xc, 4),  xc);
    pc = fmaf(c4m,  __shfl_up_sync(FULL, pc, 4),  pc);
    xc = fmaf(c8m,  __shfl_up_sync(FULL, xc, 8),  xc);
    pc = fmaf(c8m,  __shfl_up_sync(FULL, pc, 8),  pc);
    xc = fmaf(c16m, __shfl_up_sync(FULL, xc, 16), xc);
    pc = fmaf(c16m, __shfl_up_sync(FULL, pc, 16), pc);
    float xe = e0 * __shfl_up_sync(FULL, xc, 1);
    float pe = e0 * __shfl_up_sync(FULL, pc, 1);
    float xu0 = fmaf(S_C, xe, xl0),                  pu0 = fmaf(S_C, pe, pl0);
    float xu1 = fmaf(0.5f, xe, xl1),                 pu1 = fmaf(0.5f, pe, pl1);
    float xu2 = fmaf(0.35355339059327373f, xe, xl2), pu2 = fmaf(0.35355339059327373f, pe, pl2);
    float xu3 = fmaf(0.25f, xe, xl3),                pu3 = fmaf(0.25f, pe, pl3);
    float xtn = __shfl_down_sync(FULL, x[0], 1);
    float ptn = __shfl_down_sync(FULL, p[0], 1);
    x[0] = S_C * (xu0 - x[1]);   p[0] = S_C * (pu0 - p[1]);
    x[1] = S_C * (xu1 - x[2]);   p[1] = S_C * (pu1 - p[2]);
    x[2] = S_C * (xu2 - x[3]);   p[2] = S_C * (pu2 - p[3]);
    x[3] = s31 * (xu3 - m31 * xtn);
    p[3] = s31 * (pu3 - m31 * ptn);
}

// ---------------------------------------------------------------------------
// GEMM helpers
// ---------------------------------------------------------------------------
__device__ __forceinline__ void ldsm_x4(unsigned addr, unsigned& r0, unsigned& r1,
                                        unsigned& r2, unsigned& r3)
{
    asm volatile("ldmatrix.sync.aligned.m8n8.x4.shared.b16 {%0,%1,%2,%3}, [%4];"
                 : "=r"(r0), "=r"(r1), "=r"(r2), "=r"(r3) : "r"(addr));
}
__device__ __forceinline__ void mma_f16(float* d, const unsigned* a,
                                        unsigned b0, unsigned b1)
{
    asm volatile("mma.sync.aligned.m16n8k16.row.col.f32.f16.f16.f32 "
                 "{%0,%1,%2,%3}, {%4,%5,%6,%7}, {%8,%9}, {%0,%1,%2,%3};"
                 : "+f"(d[0]), "+f"(d[1]), "+f"(d[2]), "+f"(d[3])
                 : "r"(a[0]), "r"(a[1]), "r"(a[2]), "r"(a[3]), "r"(b0), "r"(b1));
}

__device__ __forceinline__ void load_A(float4 pf[8], const float* __restrict__ x,
                                       int tile, int tid)
{
    size_t m0 = (size_t)tile * M_TILE;
#pragma unroll
    for (int it = 0; it < 4; ++it) {
        int idx = tid + it * NTHREADS;
        int rr = idx >> 4, cc = idx & 15;
        const float4* g = (const float4*)(x + (m0 + rr) * NMODES + cc * 8);
        pf[2 * it]     = __ldg(g);
        pf[2 * it + 1] = __ldg(g + 1);
    }
}

__device__ __forceinline__ void convert_A(char* smem, unsigned offA,
                                          const float4 pf[8], int tid)
{
#pragma unroll
    for (int it = 0; it < 4; ++it) {
        int idx = tid + it * NTHREADS;
        int rr = idx >> 4, cc = idx & 15;
        float vs[8] = {pf[2*it].x, pf[2*it].y, pf[2*it].z, pf[2*it].w,
                       pf[2*it+1].x, pf[2*it+1].y, pf[2*it+1].z, pf[2*it+1].w};
        unsigned h[4];
#pragma unroll
        for (int k = 0; k < 4; ++k)
            asm("cvt.rn.f16x2.f32 %0, %1, %2;"
                : "=r"(h[k]) : "f"(vs[2 * k + 1]), "f"(vs[2 * k]));
        unsigned off = rr * 256 + ((cc ^ (rr & 7)) << 4);
        *(uint4*)(smem + offA + off) = make_uint4(h[0], h[1], h[2], h[3]);
    }
}

// ---------------------------------------------------------------------------
// Fused kernel: phase A (CTAs 0..31 build W) | grid barrier | phase B (GEMM)
// Phase B: SINGLE fp16 pass (y = xf @ Wf). Halves MMA work and W LDS traffic
// vs the hi/lo split; rel_err rises ~sqrt(2)x to ~5e-4 (gate 1e-3).
// ---------------------------------------------------------------------------
__global__ __launch_bounds__(NTHREADS, 2) void fused_kernel(
    const float* __restrict__ x,
    const float* __restrict__ params,
    float* __restrict__ out)
{
    extern __shared__ char smem[];
    const unsigned sbase = (unsigned)__cvta_generic_to_shared(smem);
    __shared__ float c_s[64];
    int tid = threadIdx.x, lane = tid & 31, wid = tid >> 5;
    int cta = blockIdx.x;
    const int q = cta & 1;

    // ---- everyone: issue first A-tile loads (overlaps phase A) ----
    int t = cta >> 1;
    float4 pf[8];
    load_A(pf, x, t, tid);

    // ================= phase A: build W (CTAs 0..31) =================
    if (cta < 32) {
        float4* sblk  = (float4*)(smem + OFF_A);
        float*  wpart = (float*)(smem + OFF_A + 16384);
#pragma unroll
        for (int q4 = 0; q4 < 4; ++q4) {
            int idx = tid + q4 * 256;
            int l = idx >> 7, b = idx & 127;
            float th1 = params[l * (3 * NMODES) + 3 * b + 0];
            float r   = params[l * (3 * NMODES) + 3 * b + 1];
            float th2 = params[l * (3 * NMODES) + 3 * b + 2];
            float s1, c1, s2, c2;
            __sincosf(th1, &s1, &c1);
            __sincosf(th2, &s2, &c2);
            float em = __expf(-r), ep = __expf(r);
            float A00 =  em * c1, A01 = -em * s1;
            float A10 =  ep * s1, A11 =  ep * c1;
            sblk[idx] = make_float4(c2 * A00 - s2 * A10,
                                    c2 * A01 - s2 * A11,
                                    s2 * A00 + c2 * A10,
                                    s2 * A01 + c2 * A11);
        }
        __syncthreads();

        int c = cta * 8 + wid;
        float a0   = (lane == 0)  ? 1.f : S_C;
        float c1m  = (lane >= 1)  ? 0.25f : 0.f;
        float c2m  = (lane >= 2)  ? 0.0625f : 0.f;
        float c4m  = (lane >= 4)  ? 0.00390625f : 0.f;
        float c8m  = (lane >= 8)  ? 1.52587890625e-05f : 0.f;
        float c16m = (lane >= 16) ? 2.3283064365386963e-10f : 0.f;
        float e0   = (lane == 0)  ? 0.f : 1.f;
        float s31  = (lane == 31) ? 1.f : S_C;
        float m31  = (lane == 31) ? 0.f : 1.f;

        float xx[4], pp[4];
#pragma unroll
        for (int j = 0; j < 4; ++j) {
            int b = 4 * lane + j;
            xx[j] = (c == 2 * b)     ? 1.f : 0.f;
            pp[j] = (c == 2 * b + 1) ? 1.f : 0.f;
        }
        for (int l = 0; l < NLAYERS; ++l) {
#pragma unroll
            for (int j = 0; j < 4; ++j) {
                float4 Bv = sblk[l * NMODES + 4 * lane + j];
                float nx = Bv.x * xx[j] + Bv.y * pp[j];
                float np = Bv.z * xx[j] + Bv.w * pp[j];
                xx[j] = nx; pp[j] = np;
            }
            bs_chain2(xx, pp, a0, c1m, c2m, c4m, c8m, c16m, e0, s31, m31);
        }

        if ((wid & 1) == 0) {
            int k = c >> 1;
#pragma unroll
            for (int j = 0; j < 4; ++j) {
                int b = 4 * lane + j;
                g_Wh[(2 * b)     * NMODES + k] = __float2half_rn(xx[j] * WSCALE);
                g_Wh[(2 * b + 1) * NMODES + k] = __float2half_rn(pp[j] * WSCALE);
            }
        }
#pragma unroll
        for (int j = 0; j < 4; ++j)
            wpart[wid * NMODES + 4 * lane + j] = xx[j] * xx[j] + pp[j] * pp[j];
        __syncthreads();
        if (tid < NMODES) {
            float s = 0.f;
#pragma unroll
            for (int w = 0; w < 8; ++w) s += wpart[w * NMODES + tid];
            g_part[cta * NMODES + tid] = s;
        }
    }

    // ================= grid barrier (epoch-based, replay-safe) =============
    __threadfence();
    __syncthreads();
    if (tid == 0) {
        unsigned v = atomicAdd(&g_bar, 1u);
        unsigned target = v - (v % (unsigned)GRID_P) + (unsigned)GRID_P;
        for (;;) {
            unsigned cur;
            asm volatile("ld.global.acquire.gpu.u32 %0, [%1];"
                         : "=r"(cur) : "l"(&g_bar));
            if (cur >= target) break;
            __nanosleep(128);
        }
    }
    __syncthreads();
    __threadfence();

    // ================= phase B: persistent GEMM =================
    int wm = wid & 1;          // 2 m-groups x 32 rows
    int wn = wid >> 1;         // 4 n-groups x 32 smem rows (16 modes)

    // stage this half's W with N-permutation, swizzled (32 KB)
#pragma unroll
    for (int it = 0; it < 8; ++it) {
        int idx = tid + it * NTHREADS;           // 0..2047 units of 16B
        int rr  = idx >> 4;                      // smem row 0..127
        int cc  = idx & 15;
        int g   = rr >> 5, p = rr & 31;
        int ntj = p >> 3, cx = (p >> 1) & 3, par = p & 1;
        int ml  = cx * 4 + ntj;
        int j   = q * 128 + g * 32 + 2 * ml + par;
        uint4 v = *(const uint4*)(g_Wh + j * NMODES + cc * 8);
        *(uint4*)(smem + OFF_WH + rr * 256 + ((cc ^ (rr & 7)) << 4)) = v;
    }
    if (tid < 64) {
        float s = 0.f;
#pragma unroll
        for (int cb = 0; cb < 32; ++cb)
            s += g_part[cb * NMODES + q * 64 + tid];
        c_s[tid] = 0.25f * s - 0.5f;
    }

    // ldsm lane mappings
    int a_row = (lane & 15);
    int a_cc  = (lane >> 4);
    int b_row = ((lane >> 4) << 3) + (lane & 7);
    int b_cc  = ((lane >> 3) & 1);

    const unsigned WhB = sbase + OFF_WH;

    // prologue: convert first tile, prefetch second
    convert_A(smem, OFF_A, pf, tid);
    if (t + STRIDE_T < NTILES_M) load_A(pf, x, t + STRIDE_T, tid);
    __syncthreads();

    float cvals[4];
#pragma unroll
    for (int j = 0; j < 4; ++j)
        cvals[j] = c_s[wn * 16 + (lane & 3) * 4 + j];

    int buf = 0;
    while (t < NTILES_M) {
        float acc[2][4][4];
#pragma unroll
        for (int mf = 0; mf < 2; ++mf)
#pragma unroll
            for (int j = 0; j < 4; ++j)
#pragma unroll
                for (int v = 0; v < 4; ++v) acc[mf][j][v] = 0.f;

        const unsigned AB = sbase + OFF_A + buf * 16384;
#pragma unroll
        for (int ks = 0; ks < 8; ++ks) {
            unsigned af[2][4];
#pragma unroll
            for (int mf = 0; mf < 2; ++mf) {
                int ar = wm * 32 + mf * 16 + a_row;
                int cc = 2 * ks + a_cc;
                ldsm_x4(AB + ar * 256 + ((cc ^ (ar & 7)) << 4),
                        af[mf][0], af[mf][1], af[mf][2], af[mf][3]);
            }
            unsigned bh[2][4];
#pragma unroll
            for (int p = 0; p < 2; ++p) {
                int br = wn * 32 + p * 16 + b_row;
                int cc = 2 * ks + b_cc;
                unsigned soff = br * 256 + ((cc ^ (br & 7)) << 4);
                ldsm_x4(WhB + soff, bh[p][0], bh[p][1], bh[p][2], bh[p][3]);
            }
#pragma unroll
            for (int p = 0; p < 2; ++p) {
                mma_f16(acc[0][2*p],   af[0], bh[p][0], bh[p][1]);
                mma_f16(acc[1][2*p],   af[1], bh[p][0], bh[p][1]);
                mma_f16(acc[0][2*p+1], af[0], bh[p][2], bh[p][3]);
                mma_f16(acc[1][2*p+1], af[1], bh[p][2], bh[p][3]);
            }
        }

        // convert next tile into other buffer (disjoint; no barrier)
        if (t + STRIDE_T < NTILES_M)
            convert_A(smem, OFF_A + (buf ^ 1) * 16384, pf, tid);

        // epilogue: dense STG.128 from registers (undo 1/16 W scale)
        {
            size_t m0 = (size_t)t * M_TILE;
            int mode0 = q * 64 + wn * 16 + (lane & 3) * 4;
#pragma unroll
            for (int mf = 0; mf < 2; ++mf) {
#pragma unroll
                for (int h = 0; h < 2; ++h) {
                    int row = wm * 32 + mf * 16 + (lane >> 2) + h * 8;
                    float* o = out + (m0 + row) * NMODES + mode0;
                    float v[4];
#pragma unroll
                    for (int j = 0; j < 4; ++j) {
                        float f0 = acc[mf][j][2 * h]     * WSCALE_INV;
                        float f1 = acc[mf][j][2 * h + 1] * WSCALE_INV;
                        v[j] = fmaf(f0, f0, fmaf(f1, f1, cvals[j]));
                    }
                    *(float4*)o = make_float4(v[0], v[1], v[2], v[3]);
                }
            }
        }

        // prefetch tile t+2*stride
        if (t + 2 * STRIDE_T < NTILES_M) load_A(pf, x, t + 2 * STRIDE_T, tid);

        __syncthreads();           // converts visible before next MMA loop
        t += STRIDE_T;
        buf ^= 1;
    }
}

// ---------------------------------------------------------------------------
// Launch
// ---------------------------------------------------------------------------
extern "C" void kernel_launch(void* const* d_in, const int* in_sizes, int n_in,
                              void* d_out, int out_size)
{
    const float* inputs = (const float*)d_in[0];
    const float* params = (const float*)d_in[1];
    float* out = (float*)d_out;

    cudaFuncSetAttribute(fused_kernel, cudaFuncAttributeMaxDynamicSharedMemorySize,
                         SMEM_BYTES);

    fused_kernel<<<GRID_P, NTHREADS, SMEM_BYTES>>>(inputs, params, out);
}